// round 17
// baseline (speedup 1.0000x reference)
#include <cuda_runtime.h>
#include <math.h>

#define B_ 2
#define M_ 384
#define N_ 384
#define HALF_N 192

// Shared-memory layout (float offsets)
#define OFF_S     0        // 8 copies * 640 = 5120
#define OFF_CWP   5120     // 192 * 4 corners * float2{A, packed} = 1536
#define OFF_SFOLD OFF_CWP  // 528 floats, alias: cwp dead after Phase B
#define OFF_RED   6656     // 8 (psi warp partials)
#define OFF_RED2  6664     // 16 (unscaled output partials)
#define OFF_PSI   6680     // 1 (raw psi of this half)
#define SMEM_FLOATS 6684
#define SMEM_BYTES  (SMEM_FLOATS * 4)   // 26736 B -> 6 blocks/SM

// Cross-block combine scratch (zero-init at load; self-cleaned each launch)
__device__ float    g_acc[B_ * M_ * 17];   // 16 partials + psi per m
__device__ unsigned g_cnt[B_ * M_];

__global__ __launch_bounds__(256, 6)
void equi_cts_conv_kernel(const float* __restrict__ field,
                          const float* __restrict__ center,
                          const float* __restrict__ feat,
                          const float* __restrict__ mask,
                          const float* __restrict__ kern,
                          float* __restrict__ out)
{
    extern __shared__ float sm[];
    float*  S     = sm + OFF_S;
    float4* cwp4  = (float4*)(sm + OFF_CWP);
    float2* cwp2  = (float2*)(sm + OFF_CWP);
    float*  Sfold = sm + OFF_SFOLD;            // valid only after Phase-B barrier
    float*  red   = sm + OFF_RED;
    float*  red2  = sm + OFF_RED2;
    float*  shpsi = sm + OFF_PSI;
    __shared__ int wcnt[8];

    const int tid  = threadIdx.x;
    const int lane = tid & 31;
    const int warp = tid >> 5;
    const int g    = blockIdx.x >> 1;          // (b,m) pair id
    const int half = blockIdx.x & 1;
    const int b    = g / M_;
    const int n0   = half * HALF_N;

    const float cx = center[g * 2 + 0];
    const float cy = center[g * 2 + 1];

    // ---------- Phase 0: zero S copies ----------
    {
        float4 z = make_float4(0.f, 0.f, 0.f, 0.f);
        float4* S4 = (float4*)S;
        #pragma unroll
        for (int i = tid; i < 1280; i += 256) S4[i] = z;
    }

    // ---------- Phase A1: geometry + corner weights + ballot (single round) ----------
    const bool inb = (tid < HALF_N);
    const int  nn  = n0 + (inb ? tid : 0);     // global n index
    float2 fp;
    float  mk;
    {
        const float2* fB = (const float2*)(field + (size_t)b * N_ * 2);
        const float*  mB = mask + (size_t)b * N_;
        fp = fB[nn];
        mk = mB[nn];
    }

    float psi_part = 0.f;
    float4 cwv = make_float4(0.f, 0.f, 0.f, 0.f);
    int    pack = 0;
    bool   act = false;
    if (inb) {
        float relx = (fp.x - cx) * (1.0f / 1.5f);
        float rely = (fp.y - cy) * (1.0f / 1.5f);
        float r2 = relx * relx + rely * rely;
        float s  = 1.0f - r2;
        if (s > 0.0f) {
            float att = s * s * s * mk;
            float rr;
            asm("sqrt.approx.f32 %0, %1;" : "=f"(rr) : "f"(r2 + 1e-9f));
            // theta/pi via octant-reduced poly
            float ax = fabsf(relx), ay = fabsf(rely);
            float mx = fmaxf(ax, ay), mn = fminf(ax, ay);
            float z  = (mx > 0.0f) ? __fdividef(mn, mx) : 0.0f;
            float z2 = z * z;
            float q = -0.0037310f;
            q = fmaf(q, z2,  0.0167600f);
            q = fmaf(q, z2, -0.0370620f);
            q = fmaf(q, z2,  0.0616061f);
            q = fmaf(q, z2, -0.1058772f);
            q = fmaf(q, z2,  0.3183026478f);
            q = q * z;                          // atan(z)/pi
            if (ay > ax)       q = 0.5f - q;
            if (relx < 0.0f)   q = 1.0f - q;
            q = copysignf(q, rely);             // theta/pi in [-1,1]
            float ix = 4.0f * rr - 0.5f;        // W=4
            float iy = fmaf(4.0f, q, 4.5f);     // H=10
            float x0f = floorf(ix), y0f = floorf(iy);
            float wx = ix - x0f;
            float wy = iy - y0f;
            int x0 = (int)x0f, y0 = (int)y0f;   // x0 in [-1,3], y0 in [0,8]
            float omx = 1.0f - wx, omy = 1.0f - wy;
            cwv.x = att * omx * omy;
            cwv.y = att * wx  * omy;
            cwv.z = att * omx * wy;
            cwv.w = att * wx  * wy;
            // pre-clamp: edge corners get zero weight AND a distinct dummy cell
            int xlo = x0, xhi = x0 + 1;
            if (x0 < 0)  { cwv.x = 0.f; cwv.z = 0.f; xlo = 1; }
            if (x0 >= 3) { cwv.y = 0.f; cwv.w = 0.f; xhi = 2; }
            pack = xlo | (xhi << 2) | (y0 << 4) | (nn << 8);
            psi_part += att;
            act = (att != 0.0f);
        }
    }
    unsigned ballot = __ballot_sync(0xffffffffu, act);
    if (lane == 0) wcnt[warp] = __popc(ballot);

    // psi warp-reduce
    #pragma unroll
    for (int o = 16; o; o >>= 1) psi_part += __shfl_xor_sync(0xffffffffu, psi_part, o);
    if (lane == 0) red[warp] = psi_part;
    __syncthreads();   // covers S-zeroing, wcnt, red

    // ---------- Phase A2: prefix + fully-decoded per-(n,corner) records ----------
    // record[corner] = {A_corner, cell*16 | (n*16)<<13}
    int nact;
    {
        int tot = 0, base = 0;
        #pragma unroll
        for (int s2 = 0; s2 < 8; ++s2) {
            if (s2 == warp) base = tot;
            tot += wcnt[s2];
        }
        nact = tot;
        if (act) {
            unsigned lt = (1u << lane) - 1u;
            int idx = base + __popc(ballot & lt);
            int xlo = pack & 3, xhi = (pack >> 2) & 3;
            int y0  = (pack >> 4) & 15;
            int hi  = ((pack >> 8) << 4) << 13;   // (n*16)<<13
            int rlo = y0 * 64, rhi = rlo + 64;
            cwp4[idx * 2 + 0] = make_float4(
                cwv.x, __int_as_float(hi | (rlo + xlo * 16)),
                cwv.y, __int_as_float(hi | (rlo + xhi * 16)));
            cwp4[idx * 2 + 1] = make_float4(
                cwv.z, __int_as_float(hi | (rhi + xlo * 16)),
                cwv.w, __int_as_float(hi | (rhi + xhi * 16)));
        }
        if (tid == 0) {
            float p = 0.f;
            #pragma unroll
            for (int w = 0; w < 8; ++w) p += red[w];
            shpsi[0] = p;                         // RAW psi of this half
        }
    }
    __syncthreads();

    // ---------- Phase B: scatter; pre-decoded records, depth-1 prefetch ----------
    // lane = corner(2b)*8 + pairi(3b): 32 distinct smem addrs per n.
    {
        const int corner = lane >> 3;
        const int pairi  = lane & 7;
        const int p2 = pairi * 2;
        float* Smine = S + warp * 640;
        const float* featB = feat + (size_t)b * N_ * 16 + p2;

        int k = warp;
        if (k < nact) {
            float2 e = cwp2[k * 4 + corner];
            int  pe  = __float_as_int(e.y);
            float2 f = __ldg((const float2*)(featB + (pe >> 13)));
            while (true) {
                int kn = k + 8;
                int kc = (kn < nact) ? kn : k;     // clamped prefetch
                float2 en = cwp2[kc * 4 + corner];
                int  pen  = __float_as_int(en.y);
                float2 fn = __ldg((const float2*)(featB + (pen >> 13)));
                // RMW for k
                float* sp = Smine + (pe & 8191) + p2;
                float2 sv = *(float2*)sp;
                sv.x = fmaf(e.x, f.x, sv.x);
                sv.y = fmaf(e.x, f.y, sv.y);
                *(float2*)sp = sv;
                if (kn >= nact) break;
                e = en; pe = pen; f = fn; k = kn;
            }
        }
    }
    __syncthreads();

    // ---------- Phase C1': reduce 8 copies + theta-wrap fold -> padded Sfold ----------
    // (Sfold aliases cwp — dead after Phase B.) e = (t(8), w(4), cpair(8)).
    {
        const float2* S2 = (const float2*)S;
        int e = tid;
        int cpair = e & 7;
        int w  = (e >> 3) & 3;
        int t  = e >> 5;
        int src = ((t + 1) * 4 + w) * 8 + cpair;
        float2 a = S2[src];
        #pragma unroll
        for (int c = 1; c < 8; ++c) {
            float2 v = S2[c * 320 + src];
            a.x += v.x; a.y += v.y;
        }
        if (t == 0) {
            int sw = (9 * 4 + w) * 8 + cpair;
            #pragma unroll
            for (int c = 0; c < 8; ++c) {
                float2 v = S2[c * 320 + sw];
                a.x += v.x; a.y += v.y;
            }
        }
        if (t == 7) {
            int sw = (0 * 4 + w) * 8 + cpair;
            #pragma unroll
            for (int c = 0; c < 8; ++c) {
                float2 v = S2[c * 320 + sw];
                a.x += v.x; a.y += v.y;
            }
        }
        int tw = t * 4 + w;
        Sfold[(cpair * 2 + 0) * 33 + tw] = a.x;
        Sfold[(cpair * 2 + 1) * 33 + tw] = a.y;
    }
    __syncthreads();

    // ---------- Phase C2: partial out[o,y] = sum kern * Sfold (this half) ----------
    // warp = o; lane = t*4 + y*2 + x. kern: 32 coalesced LDG.32.
    // Sfold LDS: addr = (2i+x)*33 + 4t + w -> banks (x+4t)%32: conflict-free.
    {
        const int t = lane >> 2;
        const int x = lane & 1;
        const float* kb = kern + warp * 1024;
        float acc = 0.f;
        #pragma unroll
        for (int i = 0; i < 8; ++i) {
            const float* sfr = Sfold + (i * 2 + x) * 33 + t * 4;
            #pragma unroll
            for (int w = 0; w < 4; ++w) {
                float kv = __ldg(kb + i * 128 + w * 32 + lane);
                acc = fmaf(kv, sfr[w], acc);
            }
        }
        acc += __shfl_xor_sync(0xffffffffu, acc, 1);
        acc += __shfl_xor_sync(0xffffffffu, acc, 4);
        acc += __shfl_xor_sync(0xffffffffu, acc, 8);
        acc += __shfl_xor_sync(0xffffffffu, acc, 16);
        if ((lane & ~2u) == 0) {                   // lanes 0 (y=0), 2 (y=1)
            red2[warp * 2 + (lane >> 1)] = acc;    // unscaled partial
        }
    }
    __syncthreads();

    // ---------- Phase D: cross-half combine via atomics; 2nd arriver finalizes ----------
    if (warp == 0) {
        float* accG = g_acc + g * 17;
        if (lane < 16) atomicAdd(accG + lane, red2[lane]);
        if (lane == 16) atomicAdd(accG + 16, shpsi[0]);
        __threadfence();
        unsigned old = 0;
        if (lane == 0) old = atomicAdd(&g_cnt[g], 1u);
        old = __shfl_sync(0xffffffffu, old, 0);
        if (old == 1u) {        // this block is second: totals are complete
            float tot = 0.f;
            if (lane < 17) tot = atomicAdd(accG + lane, 0.0f);   // coherent read
            float p = __shfl_sync(0xffffffffu, tot, 16);
            float inv = (p == 0.0f) ? 1.0f : 1.0f / p;
            if (lane < 16) out[g * 16 + lane] = tot * inv;
            // self-clean for next (graph-replayed) launch
            if (lane < 17) accG[lane] = 0.0f;
            if (lane == 0) g_cnt[g] = 0u;
        }
    }
}

extern "C" void kernel_launch(void* const* d_in, const int* in_sizes, int n_in,
                              void* d_out, int out_size)
{
    const float* field  = (const float*)d_in[0];
    const float* center = (const float*)d_in[1];
    const float* feat   = (const float*)d_in[2];
    const float* mask   = (const float*)d_in[3];
    const float* kern   = (const float*)d_in[4];
    float* out = (float*)d_out;

    equi_cts_conv_kernel<<<B_ * M_ * 2, 256, SMEM_BYTES>>>(field, center, feat, mask, kern, out);
}